// round 1
// baseline (speedup 1.0000x reference)
#include <cuda_runtime.h>

// WassersteinExp: per item
//   new_loc = loc + velocity
//   gamma solves  gamma*M + M*gamma = V   (M = cov1, both SPD/symmetric)
//   new_cov = M + V + gamma*M*gamma^T
// gamma is symmetric -> 6 unknowns -> 6x6 linear solve per thread,
// fully unrolled Gaussian elimination with branch-free conditional-swap
// pivoting (all static indices -> registers only).

__global__ void __launch_bounds__(256) wexp_kernel(
    const float* __restrict__ loc,
    const float* __restrict__ cov1,
    const float* __restrict__ vel,
    const float* __restrict__ vcov,
    float* __restrict__ out_loc,
    float* __restrict__ out_cov,
    int B)
{
    int i = blockIdx.x * blockDim.x + threadIdx.x;
    if (i >= B) return;

    // ---- loads ----
    const float* m = cov1 + (size_t)i * 9;
    const float* v = vcov + (size_t)i * 9;
    float a  = m[0], bb = m[1], c  = m[2];
    float d  = m[4], e  = m[5], f  = m[8];
    float v11 = v[0], v12 = v[1], v13 = v[2];
    float v22 = v[4], v23 = v[5], v33 = v[8];

    float l0 = loc[(size_t)i*3+0] + vel[(size_t)i*3+0];
    float l1 = loc[(size_t)i*3+1] + vel[(size_t)i*3+1];
    float l2 = loc[(size_t)i*3+2] + vel[(size_t)i*3+2];

    // ---- build 6x6 system A x = r for gamma = [[x0,x1,x2],[x1,x3,x4],[x2,x4,x5]] ----
    float A[6][6];
    float r[6];
    // E11
    A[0][0]=2.f*a;  A[0][1]=2.f*bb; A[0][2]=2.f*c;  A[0][3]=0.f;    A[0][4]=0.f;    A[0][5]=0.f;   r[0]=v11;
    // E12
    A[1][0]=bb;     A[1][1]=a+d;    A[1][2]=e;      A[1][3]=bb;     A[1][4]=c;      A[1][5]=0.f;   r[1]=v12;
    // E13
    A[2][0]=c;      A[2][1]=e;      A[2][2]=a+f;    A[2][3]=0.f;    A[2][4]=bb;     A[2][5]=c;     r[2]=v13;
    // E22
    A[3][0]=0.f;    A[3][1]=2.f*bb; A[3][2]=0.f;    A[3][3]=2.f*d;  A[3][4]=2.f*e;  A[3][5]=0.f;   r[3]=v22;
    // E23
    A[4][0]=0.f;    A[4][1]=c;      A[4][2]=bb;     A[4][3]=e;      A[4][4]=d+f;    A[4][5]=e;     r[4]=v23;
    // E33
    A[5][0]=0.f;    A[5][1]=0.f;    A[5][2]=2.f*c;  A[5][3]=0.f;    A[5][4]=2.f*e;  A[5][5]=2.f*f; r[5]=v33;

    // ---- Gaussian elimination, partial pivoting via conditional swaps ----
    #pragma unroll
    for (int k = 0; k < 6; ++k) {
        #pragma unroll
        for (int p = k + 1; p < 6; ++p) {
            bool sw = fabsf(A[p][k]) > fabsf(A[k][k]);
            #pragma unroll
            for (int cc = k; cc < 6; ++cc) {
                float t1 = A[k][cc], t2 = A[p][cc];
                A[k][cc] = sw ? t2 : t1;
                A[p][cc] = sw ? t1 : t2;
            }
            float t1 = r[k], t2 = r[p];
            r[k] = sw ? t2 : t1;
            r[p] = sw ? t1 : t2;
        }
        float inv = 1.0f / A[k][k];
        #pragma unroll
        for (int p = k + 1; p < 6; ++p) {
            float fac = A[p][k] * inv;
            #pragma unroll
            for (int cc = k + 1; cc < 6; ++cc)
                A[p][cc] = fmaf(-fac, A[k][cc], A[p][cc]);
            r[p] = fmaf(-fac, r[k], r[p]);
        }
    }
    float x[6];
    #pragma unroll
    for (int k = 5; k >= 0; --k) {
        float s = r[k];
        #pragma unroll
        for (int cc = k + 1; cc < 6; ++cc)
            s = fmaf(-A[k][cc], x[cc], s);
        x[k] = s / A[k][k];
    }

    // gamma = [[x0,x1,x2],[x1,x3,x4],[x2,x4,x5]]
    // T = gamma * M
    float t11 = x[0]*a  + x[1]*bb + x[2]*c;
    float t12 = x[0]*bb + x[1]*d  + x[2]*e;
    float t13 = x[0]*c  + x[1]*e  + x[2]*f;
    float t21 = x[1]*a  + x[3]*bb + x[4]*c;
    float t22 = x[1]*bb + x[3]*d  + x[4]*e;
    float t23 = x[1]*c  + x[3]*e  + x[4]*f;
    float t31 = x[2]*a  + x[4]*bb + x[5]*c;
    float t32 = x[2]*bb + x[4]*d  + x[5]*e;
    float t33 = x[2]*c  + x[4]*e  + x[5]*f;

    // G = T * gamma^T (= T * gamma); symmetric, compute upper 6
    float g11 = t11*x[0] + t12*x[1] + t13*x[2];
    float g12 = t11*x[1] + t12*x[3] + t13*x[4];
    float g13 = t11*x[2] + t12*x[4] + t13*x[5];
    float g22 = t21*x[1] + t22*x[3] + t23*x[4];
    float g23 = t21*x[2] + t22*x[4] + t23*x[5];
    float g33 = t31*x[2] + t32*x[4] + t33*x[5];

    float n11 = a  + v11 + g11;
    float n12 = bb + v12 + g12;
    float n13 = c  + v13 + g13;
    float n22 = d  + v22 + g22;
    float n23 = e  + v23 + g23;
    float n33 = f  + v33 + g33;

    // ---- stores ----
    out_loc[(size_t)i*3+0] = l0;
    out_loc[(size_t)i*3+1] = l1;
    out_loc[(size_t)i*3+2] = l2;

    float* o = out_cov + (size_t)i * 9;
    o[0] = n11; o[1] = n12; o[2] = n13;
    o[3] = n12; o[4] = n22; o[5] = n23;
    o[6] = n13; o[7] = n23; o[8] = n33;
}

extern "C" void kernel_launch(void* const* d_in, const int* in_sizes, int n_in,
                              void* d_out, int out_size)
{
    const float* loc  = (const float*)d_in[0];
    const float* cov1 = (const float*)d_in[1];
    const float* vel  = (const float*)d_in[2];
    const float* vcov = (const float*)d_in[3];

    int B = in_sizes[0] / 3;
    float* out_loc = (float*)d_out;           // [B,3]
    float* out_cov = out_loc + (size_t)B * 3; // [B,3,3]

    int threads = 256;
    int blocks  = (B + threads - 1) / threads;
    wexp_kernel<<<blocks, threads>>>(loc, cov1, vel, vcov, out_loc, out_cov, B);
}

// round 3
// speedup vs baseline: 1.0003x; 1.0003x over previous
#include <cuda_runtime.h>

// WassersteinExp: per item
//   new_loc = loc + velocity
//   gamma solves  gamma*M + M*gamma = V   (M = cov1, both SPD/symmetric)
//   new_cov = M + V + gamma*M*gamma^T
// gamma is symmetric -> 6 unknowns -> 6x6 linear solve per thread,
// fully unrolled Gaussian elimination with branch-free conditional-swap
// pivoting (all static indices -> registers only).

__global__ void __launch_bounds__(256) wexp_kernel(
    const float* __restrict__ loc,
    const float* __restrict__ cov1,
    const float* __restrict__ vel,
    const float* __restrict__ vcov,
    float* __restrict__ out_loc,
    float* __restrict__ out_cov,
    int B)
{
    int i = blockIdx.x * blockDim.x + threadIdx.x;
    if (i >= B) return;

    // ---- loads ----
    const float* m = cov1 + (size_t)i * 9;
    const float* v = vcov + (size_t)i * 9;
    float a  = m[0], bb = m[1], c  = m[2];
    float d  = m[4], e  = m[5], f  = m[8];
    float v11 = v[0], v12 = v[1], v13 = v[2];
    float v22 = v[4], v23 = v[5], v33 = v[8];

    float l0 = loc[(size_t)i*3+0] + vel[(size_t)i*3+0];
    float l1 = loc[(size_t)i*3+1] + vel[(size_t)i*3+1];
    float l2 = loc[(size_t)i*3+2] + vel[(size_t)i*3+2];

    // ---- build 6x6 system A x = r for gamma = [[x0,x1,x2],[x1,x3,x4],[x2,x4,x5]] ----
    float A[6][6];
    float r[6];
    // E11
    A[0][0]=2.f*a;  A[0][1]=2.f*bb; A[0][2]=2.f*c;  A[0][3]=0.f;    A[0][4]=0.f;    A[0][5]=0.f;   r[0]=v11;
    // E12
    A[1][0]=bb;     A[1][1]=a+d;    A[1][2]=e;      A[1][3]=bb;     A[1][4]=c;      A[1][5]=0.f;   r[1]=v12;
    // E13
    A[2][0]=c;      A[2][1]=e;      A[2][2]=a+f;    A[2][3]=0.f;    A[2][4]=bb;     A[2][5]=c;     r[2]=v13;
    // E22
    A[3][0]=0.f;    A[3][1]=2.f*bb; A[3][2]=0.f;    A[3][3]=2.f*d;  A[3][4]=2.f*e;  A[3][5]=0.f;   r[3]=v22;
    // E23
    A[4][0]=0.f;    A[4][1]=c;      A[4][2]=bb;     A[4][3]=e;      A[4][4]=d+f;    A[4][5]=e;     r[4]=v23;
    // E33
    A[5][0]=0.f;    A[5][1]=0.f;    A[5][2]=2.f*c;  A[5][3]=0.f;    A[5][4]=2.f*e;  A[5][5]=2.f*f; r[5]=v33;

    // ---- Gaussian elimination, partial pivoting via conditional swaps ----
    #pragma unroll
    for (int k = 0; k < 6; ++k) {
        #pragma unroll
        for (int p = k + 1; p < 6; ++p) {
            bool sw = fabsf(A[p][k]) > fabsf(A[k][k]);
            #pragma unroll
            for (int cc = k; cc < 6; ++cc) {
                float t1 = A[k][cc], t2 = A[p][cc];
                A[k][cc] = sw ? t2 : t1;
                A[p][cc] = sw ? t1 : t2;
            }
            float t1 = r[k], t2 = r[p];
            r[k] = sw ? t2 : t1;
            r[p] = sw ? t1 : t2;
        }
        float inv = 1.0f / A[k][k];
        #pragma unroll
        for (int p = k + 1; p < 6; ++p) {
            float fac = A[p][k] * inv;
            #pragma unroll
            for (int cc = k + 1; cc < 6; ++cc)
                A[p][cc] = fmaf(-fac, A[k][cc], A[p][cc]);
            r[p] = fmaf(-fac, r[k], r[p]);
        }
    }
    float x[6];
    #pragma unroll
    for (int k = 5; k >= 0; --k) {
        float s = r[k];
        #pragma unroll
        for (int cc = k + 1; cc < 6; ++cc)
            s = fmaf(-A[k][cc], x[cc], s);
        x[k] = s / A[k][k];
    }

    // gamma = [[x0,x1,x2],[x1,x3,x4],[x2,x4,x5]]
    // T = gamma * M
    float t11 = x[0]*a  + x[1]*bb + x[2]*c;
    float t12 = x[0]*bb + x[1]*d  + x[2]*e;
    float t13 = x[0]*c  + x[1]*e  + x[2]*f;
    float t21 = x[1]*a  + x[3]*bb + x[4]*c;
    float t22 = x[1]*bb + x[3]*d  + x[4]*e;
    float t23 = x[1]*c  + x[3]*e  + x[4]*f;
    float t31 = x[2]*a  + x[4]*bb + x[5]*c;
    float t32 = x[2]*bb + x[4]*d  + x[5]*e;
    float t33 = x[2]*c  + x[4]*e  + x[5]*f;

    // G = T * gamma^T (= T * gamma); symmetric, compute upper 6
    float g11 = t11*x[0] + t12*x[1] + t13*x[2];
    float g12 = t11*x[1] + t12*x[3] + t13*x[4];
    float g13 = t11*x[2] + t12*x[4] + t13*x[5];
    float g22 = t21*x[1] + t22*x[3] + t23*x[4];
    float g23 = t21*x[2] + t22*x[4] + t23*x[5];
    float g33 = t31*x[2] + t32*x[4] + t33*x[5];

    float n11 = a  + v11 + g11;
    float n12 = bb + v12 + g12;
    float n13 = c  + v13 + g13;
    float n22 = d  + v22 + g22;
    float n23 = e  + v23 + g23;
    float n33 = f  + v33 + g33;

    // ---- stores ----
    out_loc[(size_t)i*3+0] = l0;
    out_loc[(size_t)i*3+1] = l1;
    out_loc[(size_t)i*3+2] = l2;

    float* o = out_cov + (size_t)i * 9;
    o[0] = n11; o[1] = n12; o[2] = n13;
    o[3] = n12; o[4] = n22; o[5] = n23;
    o[6] = n13; o[7] = n23; o[8] = n33;
}

extern "C" void kernel_launch(void* const* d_in, const int* in_sizes, int n_in,
                              void* d_out, int out_size)
{
    const float* loc  = (const float*)d_in[0];
    const float* cov1 = (const float*)d_in[1];
    const float* vel  = (const float*)d_in[2];
    const float* vcov = (const float*)d_in[3];

    int B = in_sizes[0] / 3;
    float* out_loc = (float*)d_out;           // [B,3]
    float* out_cov = out_loc + (size_t)B * 3; // [B,3,3]

    int threads = 256;
    int blocks  = (B + threads - 1) / threads;
    wexp_kernel<<<blocks, threads>>>(loc, cov1, vel, vcov, out_loc, out_cov, B);
}